// round 1
// baseline (speedup 1.0000x reference)
#include <cuda_runtime.h>
#include <cstdint>

#define Bn 4
#define Cn 16
#define Kn 100
#define Hn 240
#define Wn 320
#define Pn (Hn*Wn)
#define ITERS 10
#define BW2F ((float)(0.16*0.16))

#define TPB 128
#define IPT 4
// Pn = 76800 = 128*4*150 exactly
#define XBLOCKS (Pn / (TPB * IPT))

// scratch (no allocations allowed)
__device__ float g_means[Bn*Kn*Cn];
__device__ float g_mn2[Bn*Kn];
__device__ float g_num[Bn*Kn*Cn];
__device__ float g_den[Bn*Kn];
__device__ int   g_is64;

// ---------------------------------------------------------------------------
// Detect whether seed_idx buffer is int64 or int32.
// Reads only the first 1600 bytes (valid for both layouts: int32 buffer is
// exactly 1600 bytes, int64 buffer is 3200). If the data is int32, the
// 200 int64-interpretations combine pairs of random indices -> almost surely
// out of [0, Pn). If int64, all are valid seed indices.
// ---------------------------------------------------------------------------
__global__ void detect_idx_kernel(const void* idxraw) {
    __shared__ int bad;
    if (threadIdx.x == 0) bad = 0;
    __syncthreads();
    const long long* p = (const long long*)idxraw;
    for (int i = threadIdx.x; i < 200; i += blockDim.x) {
        long long v = p[i];
        if (v < 0 || v >= (long long)Pn) bad = 1;
    }
    __syncthreads();
    if (threadIdx.x == 0) g_is64 = bad ? 0 : 1;
}

// ---------------------------------------------------------------------------
// Gather initial means from seed pixels; zero accumulators; compute mn2.
// ---------------------------------------------------------------------------
__global__ void init_means_kernel(const float* __restrict__ feat,
                                  const void* __restrict__ idxraw) {
    int t = blockIdx.x * blockDim.x + threadIdx.x;
    if (t >= Bn * Kn) return;
    int b = t / Kn;
    long long idx;
    if (g_is64) idx = ((const long long*)idxraw)[t];
    else        idx = (long long)((const int*)idxraw)[t];

    const float* fb = feat + (size_t)b * Cn * Pn + (size_t)idx;
    float mn2 = 0.0f;
#pragma unroll
    for (int c = 0; c < Cn; c++) {
        float v = fb[(size_t)c * Pn];
        g_means[t * Cn + c] = v;
        g_num[t * Cn + c] = 0.0f;
        mn2 += v * v;
    }
    g_mn2[t] = mn2;
    g_den[t] = 0.0f;
}

// ---------------------------------------------------------------------------
// One mean-shift iteration: accumulate masked sums + counts.
// Block = 128 threads x 4 points/thread. Means broadcast from smem.
// d2 = fn2 - 2*dot + mn2 (matches reference expanded form).
// ---------------------------------------------------------------------------
__global__ void __launch_bounds__(TPB)
accum_kernel(const float* __restrict__ feat) {
    __shared__ float s_m[Kn * Cn];
    __shared__ float s_mn2[Kn];
    int b = blockIdx.y;

    for (int i = threadIdx.x; i < Kn * Cn; i += TPB)
        s_m[i] = g_means[b * Kn * Cn + i];
    for (int i = threadIdx.x; i < Kn; i += TPB)
        s_mn2[i] = g_mn2[b * Kn + i];
    __syncthreads();

    const float* fb = feat + (size_t)b * Cn * Pn;
    int pbase = blockIdx.x * (TPB * IPT) + threadIdx.x;

    float f[IPT][Cn];
    float fn2[IPT];
#pragma unroll
    for (int i = 0; i < IPT; i++) {
        int p = pbase + i * TPB;
        float acc = 0.0f;
#pragma unroll
        for (int c = 0; c < Cn; c++) {
            float v = fb[(size_t)c * Pn + p];
            f[i][c] = v;
            acc += v * v;
        }
        fn2[i] = acc;
    }

    for (int k = 0; k < Kn; k++) {
        const float4 m0 = *(const float4*)&s_m[k * Cn + 0];
        const float4 m1 = *(const float4*)&s_m[k * Cn + 4];
        const float4 m2 = *(const float4*)&s_m[k * Cn + 8];
        const float4 m3 = *(const float4*)&s_m[k * Cn + 12];
        const float mk = s_mn2[k];
#pragma unroll
        for (int i = 0; i < IPT; i++) {
            float d0 = f[i][0]  * m0.x + f[i][1]  * m0.y;
            float d1 = f[i][2]  * m0.z + f[i][3]  * m0.w;
            float d2a = f[i][4] * m1.x + f[i][5]  * m1.y;
            float d3 = f[i][6]  * m1.z + f[i][7]  * m1.w;
            d0 += f[i][8]  * m2.x + f[i][9]  * m2.y;
            d1 += f[i][10] * m2.z + f[i][11] * m2.w;
            d2a += f[i][12] * m3.x + f[i][13] * m3.y;
            d3 += f[i][14] * m3.z + f[i][15] * m3.w;
            float dot = (d0 + d1) + (d2a + d3);
            float dist2 = fn2[i] - 2.0f * dot + mk;
            if (dist2 < BW2F) {
                atomicAdd(&g_den[b * Kn + k], 1.0f);
#pragma unroll
                for (int c = 0; c < Cn; c++)
                    atomicAdd(&g_num[(b * Kn + k) * Cn + c], f[i][c]);
            }
        }
    }
}

// ---------------------------------------------------------------------------
// Mean update: new = den>0 ? num / max(den,1) : old. Also zeroes accumulators
// and recomputes mn2 for the next pass.
// ---------------------------------------------------------------------------
__global__ void update_kernel() {
    int t = blockIdx.x * blockDim.x + threadIdx.x;
    if (t >= Bn * Kn) return;
    float den = g_den[t];
    float dmax = fmaxf(den, 1.0f);
    float mn2 = 0.0f;
#pragma unroll
    for (int c = 0; c < Cn; c++) {
        float old = g_means[t * Cn + c];
        float nm = (den > 0.0f) ? (g_num[t * Cn + c] / dmax) : old;
        g_means[t * Cn + c] = nm;
        g_num[t * Cn + c] = 0.0f;
        mn2 += nm * nm;
    }
    g_mn2[t] = mn2;
    g_den[t] = 0.0f;
}

// ---------------------------------------------------------------------------
// Label assignment: nearest mean (first-min tie-break, matching jnp.argmin),
// label = best_d2 < bw2 ? k+1 : 0.
// ---------------------------------------------------------------------------
__global__ void __launch_bounds__(TPB)
label_kernel(const float* __restrict__ feat, float* __restrict__ out) {
    __shared__ float s_m[Kn * Cn];
    __shared__ float s_mn2[Kn];
    int b = blockIdx.y;

    for (int i = threadIdx.x; i < Kn * Cn; i += TPB)
        s_m[i] = g_means[b * Kn * Cn + i];
    for (int i = threadIdx.x; i < Kn; i += TPB)
        s_mn2[i] = g_mn2[b * Kn + i];
    __syncthreads();

    const float* fb = feat + (size_t)b * Cn * Pn;
    int pbase = blockIdx.x * (TPB * IPT) + threadIdx.x;

    float f[IPT][Cn];
    float fn2[IPT];
#pragma unroll
    for (int i = 0; i < IPT; i++) {
        int p = pbase + i * TPB;
        float acc = 0.0f;
#pragma unroll
        for (int c = 0; c < Cn; c++) {
            float v = fb[(size_t)c * Pn + p];
            f[i][c] = v;
            acc += v * v;
        }
        fn2[i] = acc;
    }

    float best[IPT];
    int bidx[IPT];
#pragma unroll
    for (int i = 0; i < IPT; i++) { best[i] = 3.4e38f; bidx[i] = 0; }

    for (int k = 0; k < Kn; k++) {
        const float4 m0 = *(const float4*)&s_m[k * Cn + 0];
        const float4 m1 = *(const float4*)&s_m[k * Cn + 4];
        const float4 m2 = *(const float4*)&s_m[k * Cn + 8];
        const float4 m3 = *(const float4*)&s_m[k * Cn + 12];
        const float mk = s_mn2[k];
#pragma unroll
        for (int i = 0; i < IPT; i++) {
            float d0 = f[i][0]  * m0.x + f[i][1]  * m0.y;
            float d1 = f[i][2]  * m0.z + f[i][3]  * m0.w;
            float d2a = f[i][4] * m1.x + f[i][5]  * m1.y;
            float d3 = f[i][6]  * m1.z + f[i][7]  * m1.w;
            d0 += f[i][8]  * m2.x + f[i][9]  * m2.y;
            d1 += f[i][10] * m2.z + f[i][11] * m2.w;
            d2a += f[i][12] * m3.x + f[i][13] * m3.y;
            d3 += f[i][14] * m3.z + f[i][15] * m3.w;
            float dot = (d0 + d1) + (d2a + d3);
            float dist2 = fn2[i] - 2.0f * dot + mk;
            if (dist2 < best[i]) { best[i] = dist2; bidx[i] = k; }
        }
    }

#pragma unroll
    for (int i = 0; i < IPT; i++) {
        int p = pbase + i * TPB;
        out[(size_t)b * Pn + p] = (best[i] < BW2F) ? (float)(bidx[i] + 1) : 0.0f;
    }
}

// ---------------------------------------------------------------------------
// Copy converged means to the tail of d_out (guarded against out_size).
// ---------------------------------------------------------------------------
__global__ void copy_means_kernel(float* __restrict__ out, int out_size) {
    int t = blockIdx.x * blockDim.x + threadIdx.x;
    if (t < Bn * Kn * Cn && (Bn * Pn + t) < out_size)
        out[Bn * Pn + t] = g_means[t];
}

extern "C" void kernel_launch(void* const* d_in, const int* in_sizes, int n_in,
                              void* d_out, int out_size) {
    const float* feat = (const float*)d_in[0];
    const void*  sidx = d_in[1];
    float* out = (float*)d_out;

    detect_idx_kernel<<<1, 256>>>(sidx);
    init_means_kernel<<<(Bn * Kn + 127) / 128, 128>>>(feat, sidx);

    dim3 grid(XBLOCKS, Bn);
    for (int it = 0; it < ITERS; it++) {
        accum_kernel<<<grid, TPB>>>(feat);
        update_kernel<<<(Bn * Kn + 127) / 128, 128>>>();
    }

    label_kernel<<<grid, TPB>>>(feat, out);
    copy_means_kernel<<<(Bn * Kn * Cn + 255) / 256, 256>>>(out, out_size);
}

// round 2
// speedup vs baseline: 1.1124x; 1.1124x over previous
#include <cuda_runtime.h>

#define Bn 4
#define Cn 16
#define Kn 100
#define Pn 76800
#define ITERS 10
#define BW2F ((float)(0.16*0.16))

#define TPB 128
#define IPT 4                    // points per thread (2 packed pairs)
#define NP  2                    // pairs
#define XB  (Pn/(TPB*IPT))       // 150
#define ZS  4                    // k-split
#define KQ  (Kn/ZS)              // 25

typedef unsigned long long u64;

// ---- device scratch (static; no allocations) ----
__device__ float g_ms[ITERS+1][Bn*Kn*Cn];   // means entering iteration t (t=0 = seeds)
__device__ float g_num[ITERS][Bn*Kn*Cn];
__device__ float g_den[ITERS][Bn*Kn];
__device__ u64   g_best[Bn*Pn];             // packed (ordered dist bits << 32) | k
__device__ int   g_is64;

// ---- packed f32x2 helpers ----
__device__ __forceinline__ u64 pk2(float lo, float hi) {
    u64 r; asm("mov.b64 %0,{%1,%2};" : "=l"(r) : "f"(lo), "f"(hi)); return r;
}
__device__ __forceinline__ void up2(u64 v, float& lo, float& hi) {
    asm("mov.b64 {%0,%1},%2;" : "=f"(lo), "=f"(hi) : "l"(v));
}
__device__ __forceinline__ u64 f2fma(u64 a, u64 b, u64 c) {
    u64 d; asm("fma.rn.f32x2 %0,%1,%2,%3;" : "=l"(d) : "l"(a), "l"(b), "l"(c)); return d;
}
__device__ __forceinline__ u64 f2mul(u64 a, u64 b) {
    u64 d; asm("mul.rn.f32x2 %0,%1,%2;" : "=l"(d) : "l"(a), "l"(b)); return d;
}
__device__ __forceinline__ u64 f2add(u64 a, u64 b) {
    u64 d; asm("add.rn.f32x2 %0,%1,%2;" : "=l"(d) : "l"(a), "l"(b)); return d;
}
// order-preserving float -> uint map (strictly monotone)
__device__ __forceinline__ unsigned obits(float f) {
    unsigned u = __float_as_uint(f);
    return (u & 0x80000000u) ? ~u : (u | 0x80000000u);
}

// ---------------------------------------------------------------------------
// int64 vs int32 seed_idx detection (first 1600 bytes valid for both layouts)
// ---------------------------------------------------------------------------
__global__ void detect_idx_kernel(const void* idxraw) {
    __shared__ int bad;
    if (threadIdx.x == 0) bad = 0;
    __syncthreads();
    const long long* p = (const long long*)idxraw;
    for (int i = threadIdx.x; i < 200; i += blockDim.x) {
        long long v = p[i];
        if (v < 0 || v >= (long long)Pn) bad = 1;
    }
    __syncthreads();
    if (threadIdx.x == 0) g_is64 = bad ? 0 : 1;
}

// ---------------------------------------------------------------------------
// Init: zero all per-iteration accumulators, reset g_best, gather seed means.
// Must run every kernel_launch (graph replays).
// ---------------------------------------------------------------------------
__global__ void init_kernel(const float* __restrict__ feat,
                            const void* __restrict__ idxraw) {
    int t = blockIdx.x * blockDim.x + threadIdx.x;
    int stride = gridDim.x * blockDim.x;
    for (int i = t; i < Bn * Pn; i += stride) g_best[i] = ~0ull;
    float* num0 = &g_num[0][0];
    for (int i = t; i < ITERS * Bn * Kn * Cn; i += stride) num0[i] = 0.0f;
    float* den0 = &g_den[0][0];
    for (int i = t; i < ITERS * Bn * Kn; i += stride) den0[i] = 0.0f;

    if (t < Bn * Kn) {
        int b = t / Kn;
        long long idx;
        if (g_is64) idx = ((const long long*)idxraw)[t];
        else        idx = (long long)((const int*)idxraw)[t];
        const float* fb = feat + (size_t)b * Cn * Pn + (size_t)idx;
#pragma unroll
        for (int c = 0; c < Cn; c++)
            g_ms[0][t * Cn + c] = fb[(size_t)c * Pn];
    }
}

// ---------------------------------------------------------------------------
// One pass over all points for one k-quarter.
//   iter in [0,10): mean-shift accumulation into g_num/g_den[iter]
//   iter == 10:     label pass -> atomicMin of packed (dist,k) into g_best
// Block start: rebuild means[iter] from (means[iter-1], num/den[iter-1]) in
// smem (duplicated f32x2 layout); block x==0 persists them to g_ms[iter].
// ---------------------------------------------------------------------------
__global__ void __launch_bounds__(TPB)
pass_kernel(const float* __restrict__ feat, int iter) {
    __shared__ __align__(16) u64 s_m2[KQ * Cn];   // {m,m} duplicated
    __shared__ u64 s_mn2[KQ];                     // {mn2,mn2}
    const int b = blockIdx.y;
    const int k0 = blockIdx.z * KQ;

    // ---- update phase: build means for this k-quarter ----
    for (int kl = threadIdx.x; kl < KQ; kl += TPB) {
        int kg = k0 + kl;
        int base = (b * Kn + kg) * Cn;
        float mn2 = 0.0f;
        if (iter == 0) {
#pragma unroll
            for (int c = 0; c < Cn; c++) {
                float m = g_ms[0][base + c];
                s_m2[kl * Cn + c] = pk2(m, m);
                mn2 += m * m;
            }
        } else {
            float den = g_den[iter - 1][b * Kn + kg];
            float dm = fmaxf(den, 1.0f);
            bool pos = den > 0.0f;
#pragma unroll
            for (int c = 0; c < Cn; c++) {
                float old = g_ms[iter - 1][base + c];
                float nm = pos ? (g_num[iter - 1][base + c] / dm) : old;
                s_m2[kl * Cn + c] = pk2(nm, nm);
                mn2 += nm * nm;
                if (blockIdx.x == 0) g_ms[iter][base + c] = nm;
            }
        }
        s_mn2[kl] = pk2(mn2, mn2);
    }
    __syncthreads();

    // ---- load 4 consecutive points as 2 packed pairs via LDG.128 ----
    const int pbase = blockIdx.x * (TPB * IPT) + 4 * threadIdx.x;
    const ulonglong2* fb2 =
        (const ulonglong2*)(feat + (size_t)b * Cn * Pn + pbase);
    u64 fp[NP][Cn];
    u64 fn2a = 0, fn2b = 0;
#pragma unroll
    for (int c = 0; c < Cn; c++) {
        ulonglong2 v = fb2[(size_t)c * (Pn / 4)];
        fp[0][c] = v.x;
        fp[1][c] = v.y;
        fn2a = c ? f2fma(v.x, v.x, fn2a) : f2mul(v.x, v.x);
        fn2b = c ? f2fma(v.y, v.y, fn2b) : f2mul(v.y, v.y);
    }
    u64 fn2p[NP] = {fn2a, fn2b};

    const u64 N2 = pk2(-2.0f, -2.0f);
    const bool lab = (iter == ITERS);
    float best[IPT];
    int bidx[IPT];
#pragma unroll
    for (int i = 0; i < IPT; i++) { best[i] = 3.4e38f; bidx[i] = 0; }

    for (int kl = 0; kl < KQ; kl++) {
        const ulonglong2* mp = (const ulonglong2*)&s_m2[kl * Cn];
        ulonglong2 m01 = mp[0], m23 = mp[1], m45 = mp[2], m67 = mp[3];
        ulonglong2 m89 = mp[4], mab = mp[5], mcd = mp[6], mef = mp[7];
        u64 mk = s_mn2[kl];
#pragma unroll
        for (int pr = 0; pr < NP; pr++) {
            u64 a0 = f2fma(fp[pr][1], m01.y, f2mul(fp[pr][0], m01.x));
            u64 a1 = f2fma(fp[pr][3], m23.y, f2mul(fp[pr][2], m23.x));
            u64 a2 = f2fma(fp[pr][5], m45.y, f2mul(fp[pr][4], m45.x));
            u64 a3 = f2fma(fp[pr][7], m67.y, f2mul(fp[pr][6], m67.x));
            a0 = f2fma(fp[pr][9],  m89.y, f2fma(fp[pr][8],  m89.x, a0));
            a1 = f2fma(fp[pr][11], mab.y, f2fma(fp[pr][10], mab.x, a1));
            a2 = f2fma(fp[pr][13], mcd.y, f2fma(fp[pr][12], mcd.x, a2));
            a3 = f2fma(fp[pr][15], mef.y, f2fma(fp[pr][14], mef.x, a3));
            u64 dot = f2add(f2add(a0, a1), f2add(a2, a3));
            u64 dist = f2add(f2fma(dot, N2, fn2p[pr]), mk);
            float dlo, dhi;
            up2(dist, dlo, dhi);
            if (!lab) {
                if (dlo < BW2F) {
                    int kg = k0 + kl;
                    atomicAdd(&g_den[iter][b * Kn + kg], 1.0f);
#pragma unroll
                    for (int c = 0; c < Cn; c++) {
                        float v0, v1; up2(fp[pr][c], v0, v1);
                        atomicAdd(&g_num[iter][(b * Kn + kg) * Cn + c], v0);
                    }
                }
                if (dhi < BW2F) {
                    int kg = k0 + kl;
                    atomicAdd(&g_den[iter][b * Kn + kg], 1.0f);
#pragma unroll
                    for (int c = 0; c < Cn; c++) {
                        float v0, v1; up2(fp[pr][c], v0, v1);
                        atomicAdd(&g_num[iter][(b * Kn + kg) * Cn + c], v1);
                    }
                }
            } else {
                if (dlo < best[2 * pr])     { best[2 * pr] = dlo;     bidx[2 * pr] = k0 + kl; }
                if (dhi < best[2 * pr + 1]) { best[2 * pr + 1] = dhi; bidx[2 * pr + 1] = k0 + kl; }
            }
        }
    }

    if (lab) {
#pragma unroll
        for (int i = 0; i < IPT; i++) {
            int pr = i >> 1, h = i & 1;
            int p = pbase + 2 * pr + h;
            u64 v = ((u64)obits(best[i]) << 32) | (unsigned)bidx[i];
            atomicMin(&g_best[b * Pn + p], v);
        }
    }
}

// ---------------------------------------------------------------------------
// Finalize: labels from g_best; converged means (g_ms[10]) to the tail.
// Strictly-ordered bit compare reproduces (best_d2 < bw2) exactly.
// ---------------------------------------------------------------------------
__global__ void finalize_kernel(float* __restrict__ out, int out_size) {
    int t = blockIdx.x * blockDim.x + threadIdx.x;
    unsigned thr = obits(BW2F);
    if (t < Bn * Pn) {
        u64 v = g_best[t];
        unsigned db = (unsigned)(v >> 32);
        unsigned kk = (unsigned)v;
        out[t] = (db < thr) ? (float)(kk + 1) : 0.0f;
    }
    if (t < Bn * Kn * Cn && (Bn * Pn + t) < out_size)
        out[Bn * Pn + t] = g_ms[ITERS][t];
}

extern "C" void kernel_launch(void* const* d_in, const int* in_sizes, int n_in,
                              void* d_out, int out_size) {
    const float* feat = (const float*)d_in[0];
    const void*  sidx = d_in[1];
    float* out = (float*)d_out;

    detect_idx_kernel<<<1, 256>>>(sidx);
    init_kernel<<<300, 256>>>(feat, sidx);

    dim3 grid(XB, Bn, ZS);
    for (int it = 0; it <= ITERS; it++)
        pass_kernel<<<grid, TPB>>>(feat, it);

    finalize_kernel<<<(Bn * Pn + 255) / 256, 256>>>(out, out_size);
}